// round 14
// baseline (speedup 1.0000x reference)
#include <cuda_runtime.h>
#include <cstdint>
#include <math.h>

// ---------------- constants ----------------
#define T_STEPS 256
#define BS      16
#define IN_DIM  64
#define LAT     256
#define OUT_DIM 32
#define NPART   128
#define C32LOG2PI 58.81206612509905f

// ---------------- device scratch (no cudaMalloc allowed) ----------------
__device__ float d_gi  [T_STEPS*BS*192];       // 3*IN gates for input GRU
__device__ float d_upA [T_STEPS*BS*IN_DIM];
__device__ float d_upB [T_STEPS*BS*IN_DIM];
__device__ float d_giP [T_STEPS*BS*768];       // 3*LAT input gates for particle cell
__device__ float d_gwhhT[LAT*768];             // g_whh transposed [256][768]
__device__ float d_fw1T [LAT*LAT];             // f_w1 transposed  [256][256]
__device__ float d_fw2T [LAT*OUT_DIM];         // f_w2 transposed  [256][32]
__device__ float d_x   [2][BS*NPART*LAT];      // particle ping-pong
__device__ int   d_idx [BS*NPART];
__device__ float d_vary[OUT_DIM];
__device__ float d_stdx[LAT];
__device__ float d_slv;

// ---------------- threefry2x32 (JAX-exact, integer => always exact) --------
__host__ __device__ __forceinline__ void tf2x32(uint32_t k0, uint32_t k1,
                                                uint32_t x0, uint32_t x1,
                                                uint32_t& o0, uint32_t& o1) {
    uint32_t ks0 = k0, ks1 = k1, ks2 = 0x1BD11BDAu ^ k0 ^ k1;
    x0 += ks0; x1 += ks1;
#define TFR(r) { x0 += x1; x1 = (x1 << (r)) | (x1 >> (32 - (r))); x1 ^= x0; }
    TFR(13) TFR(15) TFR(26) TFR(6)   x0 += ks1; x1 += ks2 + 1u;
    TFR(17) TFR(29) TFR(16) TFR(24)  x0 += ks2; x1 += ks0 + 2u;
    TFR(13) TFR(15) TFR(26) TFR(6)   x0 += ks0; x1 += ks1 + 3u;
    TFR(17) TFR(29) TFR(16) TFR(24)  x0 += ks1; x1 += ks2 + 4u;
    TFR(13) TFR(15) TFR(26) TFR(6)   x0 += ks2; x1 += ks0 + 5u;
#undef TFR
    o0 = x0; o1 = x1;
}

// partitionable random_bits (32-bit): element e -> tf(key, hi=0, lo=e), XOR halves
__device__ __forceinline__ uint32_t jax_bits32(uint32_t k0, uint32_t k1, uint32_t e) {
    uint32_t o0, o1;
    tf2x32(k0, k1, 0u, e, o0, o1);
    return o0 ^ o1;
}

// ---------------- XLA fast tanh — GPU variant (with_fma, clamp 7.99881) ----
__device__ __forceinline__ float xla_tanh(float x) {
    float ax = fabsf(x);
    float xc = fminf(fmaxf(x, -7.99881172180175781f), 7.99881172180175781f);
    float x2 = __fmul_rn(xc, xc);
    float num = -2.76076847742355e-16f;
    num = __fmaf_rn(x2, num, 2.00018790482477e-13f);
    num = __fmaf_rn(x2, num, -8.60467152213735e-11f);
    num = __fmaf_rn(x2, num, 5.12229709037114e-08f);
    num = __fmaf_rn(x2, num, 1.48572235717979e-05f);
    num = __fmaf_rn(x2, num, 6.37261928875436e-04f);
    num = __fmaf_rn(x2, num, 4.89352455891786e-03f);
    num = __fmul_rn(xc, num);
    float den = 1.19825839466702e-06f;
    den = __fmaf_rn(x2, den, 1.18534705686654e-04f);
    den = __fmaf_rn(x2, den, 2.26843463243900e-03f);
    den = __fmaf_rn(x2, den, 4.89352518554385e-03f);
    return (ax < 0.0004f) ? x : __fdiv_rn(num, den);
}

// LogisticExpander with GPU fp-contraction: 0.5 + 0.5*t -> fma(0.5, t, 0.5)
__device__ __forceinline__ float xla_logistic(float x) {
    return __fmaf_rn(0.5f, xla_tanh(__fmul_rn(0.5f, x)), 0.5f);
}

// XLA f32 erf_inv polynomial — FMA Horner (GPU contraction), log1p libdevice
__device__ __forceinline__ float erfinv_xla(float x) {
    float x2 = __fmul_rn(x, x);
    float w = -log1pf(-x2);
    float p;
    if (w < 5.f) {
        w = __fsub_rn(w, 2.5f);
        p = 2.81022636e-08f;
        p = __fmaf_rn(p, w, 3.43273939e-07f);
        p = __fmaf_rn(p, w, -3.5233877e-06f);
        p = __fmaf_rn(p, w, -4.39150654e-06f);
        p = __fmaf_rn(p, w, 0.00021858087f);
        p = __fmaf_rn(p, w, -0.00125372503f);
        p = __fmaf_rn(p, w, -0.00417768164f);
        p = __fmaf_rn(p, w, 0.246640727f);
        p = __fmaf_rn(p, w, 1.50140941f);
    } else {
        w = __fsub_rn(sqrtf(w), 3.f);
        p = -0.000200214257f;
        p = __fmaf_rn(p, w, 0.000100950558f);
        p = __fmaf_rn(p, w, 0.00134934322f);
        p = __fmaf_rn(p, w, -0.00367342844f);
        p = __fmaf_rn(p, w, 0.00573950773f);
        p = __fmaf_rn(p, w, -0.0076224613f);
        p = __fmaf_rn(p, w, 0.00943887047f);
        p = __fmaf_rn(p, w, 1.00167406f);
        p = __fmaf_rn(p, w, 2.83297682f);
    }
    return __fmul_rn(p, x);
}

// jax.random.normal from raw bits: uniform(lo,1) then sqrt(2)*erfinv
__device__ __forceinline__ float jax_normal_bits(uint32_t bits) {
    float f = __fsub_rn(__uint_as_float((bits >> 9) | 0x3f800000u), 1.0f);
    const float lo = -0.99999994f;                 // nextafter(-1,0); hi-lo -> 2.0f
    float v = __fmaf_rn(f, 2.0f, lo);              // contracted (exact either way)
    v = fmaxf(lo, v);
    return __fmul_rn(1.41421356237309515f, erfinv_xla(v)); // f32(sqrt(2))
}

// ---------------- prep: transposes + variance terms ----------------
__global__ void prep_kernel(const float* __restrict__ g_whh,
                            const float* __restrict__ f_w1,
                            const float* __restrict__ f_w2,
                            const float* __restrict__ lvx,
                            const float* __restrict__ lvy) {
    int idx = blockIdx.x * blockDim.x + threadIdx.x;
    int stride = gridDim.x * blockDim.x;
    for (int i = idx; i < 768 * LAT; i += stride) {
        int r = i / LAT, c = i % LAT;
        d_gwhhT[c * 768 + r] = g_whh[i];
    }
    for (int i = idx; i < LAT * LAT; i += stride) {
        int r = i / LAT, c = i % LAT;
        d_fw1T[c * LAT + r] = f_w1[i];
    }
    for (int i = idx; i < OUT_DIM * LAT; i += stride) {
        int r = i / LAT, c = i % LAT;
        d_fw2T[c * OUT_DIM + r] = f_w2[i];
    }
    for (int i = idx; i < OUT_DIM; i += stride) d_vary[i] = expf(lvy[i]);   // libdevice
    for (int i = idx; i < LAT; i += stride) d_stdx[i] = expf(__fmul_rn(0.5f, lvx[i]));
    if (idx == 0) {
        float s = 0.f;
        for (int o = 0; o < OUT_DIM; o++) s = __fadd_rn(s, lvy[o]);
        d_slv = s;   // common shift across particles — order cancels in argmax
    }
}

// ---------------- input GRU: gi = X @ Wih^T (fma, ascending k), then + bih --
__global__ void gi_gemm_kernel(const float* __restrict__ X,
                               const float* __restrict__ W,
                               const float* __restrict__ bias,
                               float* __restrict__ out) {
    __shared__ float xs[IN_DIM];
    int row = blockIdx.x, j = threadIdx.x;   // 192 threads
    if (j < IN_DIM) xs[j] = X[row * IN_DIM + j];
    __syncthreads();
    float acc = 0.f;
#pragma unroll 8
    for (int k = 0; k < IN_DIM; k++) acc = __fmaf_rn(xs[k], __ldg(&W[j * IN_DIM + k]), acc);
    out[(size_t)row * 192 + j] = __fadd_rn(acc, bias[j]);
}

// ---------------- input GRU recurrence (one block per batch) ----------------
__global__ void gru_rec_kernel(const float* __restrict__ gi,
                               const float* __restrict__ Whh,
                               const float* __restrict__ bhh,
                               float* __restrict__ up) {
    __shared__ float h[IN_DIM];
    __shared__ float gh[192];
    int b = blockIdx.x, j = threadIdx.x;   // 192 threads
    if (j < IN_DIM) h[j] = 0.f;
    __syncthreads();
    float bj = bhh[j];
    for (int t = 0; t < T_STEPS; t++) {
        float acc = 0.f;
#pragma unroll 8
        for (int k = 0; k < IN_DIM; k++) acc = __fmaf_rn(h[k], __ldg(&Whh[j * IN_DIM + k]), acc);
        gh[j] = __fadd_rn(acc, bj);        // dot then + bhh (separate rounding)
        __syncthreads();
        if (j < IN_DIM) {
            const float* g = gi + (size_t)(t * BS + b) * 192;
            float r = xla_logistic(__fadd_rn(g[j], gh[j]));
            float z = xla_logistic(__fadd_rn(g[IN_DIM + j], gh[IN_DIM + j]));
            // n = tanh(inn + r*hn) -> fma(r, hn, inn)  (GPU contraction)
            float nn = xla_tanh(__fmaf_rn(r, gh[2 * IN_DIM + j], g[2 * IN_DIM + j]));
            // (1-z)*n + z*h -> fma(1-z, n, mul(z,h))   (GPU contraction)
            float zh = __fmul_rn(z, h[j]);
            float hv = __fmaf_rn(__fsub_rn(1.f, z), nn, zh);
            h[j] = hv;
            up[(size_t)(t * BS + b) * IN_DIM + j] = hv;
        }
        __syncthreads();
    }
}

// ---------------- particle-cell input gates: giP = up @ g_wih^T, + g_bih ----
__global__ void gip_gemm_kernel(const float* __restrict__ X,
                                const float* __restrict__ W,
                                const float* __restrict__ bias,
                                float* __restrict__ out) {
    __shared__ float xs[IN_DIM];
    int row = blockIdx.x, j = threadIdx.x;  // 768 threads
    if (j < IN_DIM) xs[j] = X[row * IN_DIM + j];
    __syncthreads();
    float acc = 0.f;
#pragma unroll 8
    for (int k = 0; k < IN_DIM; k++) acc = __fmaf_rn(xs[k], __ldg(&W[j * IN_DIM + k]), acc);
    out[(size_t)row * 768 + j] = __fadd_rn(acc, bias[j]);
}

// ---------------- resample: logp (warp-tree sum) + gumbel argmax ------------
__global__ void resample_kernel(const float* __restrict__ out,
                                const float* __restrict__ y,
                                int k, uint32_t rk0, uint32_t rk1) {
    __shared__ float lp[NPART];
    int b = blockIdx.x, tid = threadIdx.x;   // 512 threads = 16 warps
    int w = tid >> 5, lane = tid & 31;

    // logp: one warp per particle; lane o holds diff^2/var term; shfl-down tree
    const float* yp = y + (size_t)((k - 1) * BS + b) * OUT_DIM;
    float ypv = yp[lane];
    float vv = d_vary[lane];
    for (int p = w; p < NPART; p += 16) {
        const float* yh = out + (size_t)(((k - 1) * BS + b) * NPART + p) * OUT_DIM;
        float d = __fsub_rn(yh[lane], ypv);
        float v = __fdiv_rn(__fmul_rn(d, d), vv);
#pragma unroll
        for (int off = 16; off; off >>= 1)
            v = __fadd_rn(v, __shfl_down_sync(0xffffffffu, v, off));
        if (lane == 0)
            lp[p] = __fmul_rn(-0.5f, __fadd_rn(__fadd_rn(v, d_slv), C32LOG2PI));
    }
    __syncthreads();

    // gumbel + argmax (first-index tie-break)
    for (int p = w; p < NPART; p += 16) {
        float best = -3.4e38f; int bi = 0;
#pragma unroll
        for (int q = 0; q < 4; q++) {
            int n = lane * 4 + q;
            // gumbel element index in (16,128,128): e = (b*128+p)*128 + n
            uint32_t e = ((uint32_t)(b * NPART + p) << 7) | (uint32_t)n;
            uint32_t bits = jax_bits32(rk0, rk1, e);   // partitionable stream
            float f = __fsub_rn(__uint_as_float((bits >> 9) | 0x3f800000u), 1.0f);
            float val = __fadd_rn(__fmul_rn(f, 1.0f), 1.17549435e-38f);
            val = fmaxf(1.17549435e-38f, val);
            float l1 = logf(val);                      // libdevice __nv_logf
            float g = -logf(-l1);
            float tot = __fadd_rn(g, lp[n]);
            if (tot > best) { best = tot; bi = n; }
        }
        for (int off = 16; off; off >>= 1) {
            float ov = __shfl_down_sync(0xffffffffu, best, off);
            int   oi = __shfl_down_sync(0xffffffffu, bi, off);
            if (ov > best || (ov == best && oi < bi)) { best = ov; bi = oi; }
        }
        if (lane == 0) d_idx[b * NPART + p] = bi;
    }
}

// ---------------- fused particle update: gather + GRU cell + noise + FFN ----
__global__ void __launch_bounds__(256, 1)
update_kernel(int k, int first,
              const float* __restrict__ xprev, float* __restrict__ xnew,
              float* __restrict__ out,
              uint32_t nk0, uint32_t nk1,
              const float* __restrict__ g_bhh,
              const float* __restrict__ f_b1,
              const float* __restrict__ f_b2) {
    __shared__ float R1[256 * 17];   // gathered H, later FFN1 hidden
    __shared__ float R2[256 * 17];   // x (post-noise)
    int j = threadIdx.x;             // 256 threads (= latent dim)
    int b = blockIdx.y, p0 = blockIdx.x * 16;

    // gather resampled particles (transposed into smem)
    if (first) {
#pragma unroll
        for (int p = 0; p < 16; p++) R1[j * 17 + p] = 0.f;
    } else {
#pragma unroll
        for (int p = 0; p < 16; p++) {
            int ip = d_idx[b * NPART + p0 + p];
            R1[j * 17 + p] = xprev[(size_t)(b * NPART + ip) * LAT + j];
        }
    }
    __syncthreads();

    // gh = h @ g_whh^T  (ascending k, single accumulator, fma)
    float ar[16], az[16], an[16];
#pragma unroll
    for (int p = 0; p < 16; p++) { ar[p] = 0.f; az[p] = 0.f; an[p] = 0.f; }
    if (!first) {
#pragma unroll 4
        for (int l = 0; l < LAT; l++) {
            float wr = d_gwhhT[l * 768 + j];
            float wz = d_gwhhT[l * 768 + 256 + j];
            float wn = d_gwhhT[l * 768 + 512 + j];
#pragma unroll
            for (int p = 0; p < 16; p++) {
                float hv = R1[l * 17 + p];
                ar[p] = __fmaf_rn(wr, hv, ar[p]);
                az[p] = __fmaf_rn(wz, hv, az[p]);
                an[p] = __fmaf_rn(wn, hv, an[p]);
            }
        }
    }

    // gates + noise — GPU-contracted elementwise forms
    const float* gib = d_giP + (size_t)(k * BS + b) * 768;
    float ir = gib[j], iz = gib[256 + j], inn = gib[512 + j];
    float br = g_bhh[j], bz = g_bhh[256 + j], bn = g_bhh[512 + j];
    float sx = d_stdx[j];
#pragma unroll
    for (int p = 0; p < 16; p++) {
        float ghr = __fadd_rn(ar[p], br);
        float ghz = __fadd_rn(az[p], bz);
        float ghn = __fadd_rn(an[p], bn);
        float r = xla_logistic(__fadd_rn(ir, ghr));
        float z = xla_logistic(__fadd_rn(iz, ghz));
        float nn = xla_tanh(__fmaf_rn(r, ghn, inn));       // fma(r, hn, inn)
        float hp = first ? 0.f : R1[j * 17 + p];
        float zh = __fmul_rn(z, hp);
        float xv = __fmaf_rn(__fsub_rn(1.f, z), nn, zh);   // fma(1-z, n, z*h)
        // normal element index in (16,128,256): e = (b*128+p)*256 + j
        uint32_t e = ((uint32_t)(b * NPART + p0 + p) << 8) | (uint32_t)j;
        uint32_t bits = jax_bits32(nk0, nk1, e);           // partitionable stream
        xv = __fmaf_rn(jax_normal_bits(bits), sx, xv);     // fma(n, std, x)
        xnew[(size_t)(b * NPART + p0 + p) * LAT + j] = xv;
        R2[j * 17 + p] = xv;
    }
    __syncthreads();

    // FFN layer 1: hidden = relu(x @ f_w1^T + b1)
    float a2[16];
#pragma unroll
    for (int p = 0; p < 16; p++) a2[p] = 0.f;
#pragma unroll 4
    for (int l = 0; l < LAT; l++) {
        float w = d_fw1T[l * LAT + j];
#pragma unroll
        for (int p = 0; p < 16; p++) a2[p] = __fmaf_rn(w, R2[l * 17 + p], a2[p]);
    }
    float bb1 = f_b1[j];
#pragma unroll
    for (int p = 0; p < 16; p++) R1[j * 17 + p] = fmaxf(__fadd_rn(a2[p], bb1), 0.f);
    __syncthreads();

    // FFN layer 2: y = hidden @ f_w2^T + b2 — sequential k per output element
    int o = j & 31, ph = j >> 5;
    float bo = f_b2[o];
#pragma unroll
    for (int t = 0; t < 2; t++) {
        int p = ph + t * 8;
        float acc = 0.f;
#pragma unroll 8
        for (int l = 0; l < LAT; l++)
            acc = __fmaf_rn(d_fw2T[l * OUT_DIM + o], R1[l * 17 + p], acc);
        out[(size_t)((k * BS + b) * NPART + p0 + p) * OUT_DIM + o] = __fadd_rn(acc, bo);
    }
}

// ---------------- host ----------------
extern "C" void kernel_launch(void* const* d_in, const int* in_sizes, int n_in,
                              void* d_out, int out_size) {
    const float *u = 0, *y = 0, *g_wih = 0, *g_whh = 0, *g_bih = 0, *g_bhh = 0;
    const float *f_w1 = 0, *f_b1 = 0, *f_w2 = 0, *f_b2 = 0, *lvx = 0, *lvy = 0;
    const float *wih[3] = {0, 0, 0}, *whh[3] = {0, 0, 0}, *bih[3] = {0, 0, 0}, *bhh[3] = {0, 0, 0};
    int c12288 = 0, c192 = 0, c768 = 0, c256 = 0, c32 = 0;
    for (int i = 0; i < n_in; i++) {
        int s = in_sizes[i];
        const float* p = (const float*)d_in[i];
        if (s == 262144) u = p;
        else if (s == 131072) y = p;
        else if (s == 49152) g_wih = p;
        else if (s == 196608) g_whh = p;
        else if (s == 768) { if (c768++ == 0) g_bih = p; else g_bhh = p; }
        else if (s == 65536) f_w1 = p;
        else if (s == 8192) f_w2 = p;
        else if (s == 256) { if (c256++ == 0) f_b1 = p; else lvx = p; }
        else if (s == 32) { if (c32++ == 0) f_b2 = p; else lvy = p; }
        else if (s == 12288) { int t = c12288++; if ((t & 1) == 0) wih[t / 2] = p; else whh[t / 2] = p; }
        else if (s == 192) { int t = c192++; if ((t & 1) == 0) bih[t / 2] = p; else bhh[t / 2] = p; }
    }

    // JAX key derivation (threefry_partitionable, JAX >= 0.5):
    //   base = key(42) -> [0,42];  fold_in(base,m) = tf(base, 0, m)
    //   split(key,T)[t] = tf(key, 0, t)   (foldlike)
    uint32_t kr0, kr1, kn0, kn1;
    tf2x32(0u, 42u, 0u, 1u, kr0, kr1);
    tf2x32(0u, 42u, 0u, 2u, kn0, kn1);
    static uint32_t rk[T_STEPS][2], nk[T_STEPS][2];
    for (int t = 0; t < T_STEPS; t++) {
        tf2x32(kr0, kr1, 0u, (uint32_t)t, rk[t][0], rk[t][1]);
        tf2x32(kn0, kn1, 0u, (uint32_t)t, nk[t][0], nk[t][1]);
    }

    void *pgi, *pupA, *pupB, *pgiP, *px;
    cudaGetSymbolAddress(&pgi, d_gi);
    cudaGetSymbolAddress(&pupA, d_upA);
    cudaGetSymbolAddress(&pupB, d_upB);
    cudaGetSymbolAddress(&pgiP, d_giP);
    cudaGetSymbolAddress(&px, d_x);
    float* gi = (float*)pgi;
    float* upA = (float*)pupA;
    float* upB = (float*)pupB;
    float* giP = (float*)pgiP;
    float* xb = (float*)px;
    float* xbuf[2] = {xb, xb + BS * NPART * LAT};
    float* fout = (float*)d_out;

    prep_kernel<<<128, 256>>>(g_whh, f_w1, f_w2, lvx, lvy);

    // 3-layer input GRU
    gi_gemm_kernel<<<T_STEPS * BS, 192>>>(u, wih[0], bih[0], gi);
    gru_rec_kernel<<<BS, 192>>>(gi, whh[0], bhh[0], upA);
    gi_gemm_kernel<<<T_STEPS * BS, 192>>>(upA, wih[1], bih[1], gi);
    gru_rec_kernel<<<BS, 192>>>(gi, whh[1], bhh[1], upB);
    gi_gemm_kernel<<<T_STEPS * BS, 192>>>(upB, wih[2], bih[2], gi);
    gru_rec_kernel<<<BS, 192>>>(gi, whh[2], bhh[2], upA);

    // particle-cell input gates for all steps
    gip_gemm_kernel<<<T_STEPS * BS, 768>>>(upA, g_wih, g_bih, giP);

    // sequential particle filter
    for (int k = 0; k < T_STEPS; k++) {
        if (k > 0)
            resample_kernel<<<BS, 512>>>(fout, y, k, rk[k][0], rk[k][1]);
        int cur = k & 1, prev = cur ^ 1;
        update_kernel<<<dim3(8, BS), 256>>>(k, (k == 0) ? 1 : 0,
                                            xbuf[prev], xbuf[cur], fout,
                                            nk[k][0], nk[k][1],
                                            g_bhh, f_b1, f_b2);
    }
}

// round 15
// speedup vs baseline: 1.6914x; 1.6914x over previous
#include <cuda_runtime.h>
#include <cstdint>
#include <math.h>

// ---------------- constants ----------------
#define T_STEPS 256
#define BS      16
#define IN_DIM  64
#define LAT     256
#define OUT_DIM 32
#define NPART   128
#define C32LOG2PI 58.81206612509905f

// ---------------- device scratch (no cudaMalloc allowed) ----------------
__device__ float d_gi  [T_STEPS*BS*192];       // 3*IN gates for input GRU
__device__ float d_upA [T_STEPS*BS*IN_DIM];
__device__ float d_upB [T_STEPS*BS*IN_DIM];
__device__ float d_giP [T_STEPS*BS*768];       // 3*LAT input gates for particle cell
__device__ float d_gwhhT[LAT*768];             // g_whh transposed [256][768]
__device__ float d_fw1T [LAT*LAT];             // f_w1 transposed  [256][256]
__device__ float d_fw2T [LAT*OUT_DIM];         // f_w2 transposed  [256][32]
__device__ float d_wihT [3][IN_DIM*192];       // w_ih_l transposed [64][192]
__device__ float d_whhT [3][IN_DIM*192];       // w_hh_l transposed [64][192]
__device__ float d_gwihT[IN_DIM*768];          // g_wih transposed  [64][768]
__device__ float d_x   [2][BS*NPART*LAT];      // particle ping-pong
__device__ float d_vary[OUT_DIM];
__device__ float d_stdx[LAT];
__device__ float d_slv;

// ---------------- threefry2x32 (JAX-exact) ---------------------------------
__host__ __device__ __forceinline__ void tf2x32(uint32_t k0, uint32_t k1,
                                                uint32_t x0, uint32_t x1,
                                                uint32_t& o0, uint32_t& o1) {
    uint32_t ks0 = k0, ks1 = k1, ks2 = 0x1BD11BDAu ^ k0 ^ k1;
    x0 += ks0; x1 += ks1;
#define TFR(r) { x0 += x1; x1 = (x1 << (r)) | (x1 >> (32 - (r))); x1 ^= x0; }
    TFR(13) TFR(15) TFR(26) TFR(6)   x0 += ks1; x1 += ks2 + 1u;
    TFR(17) TFR(29) TFR(16) TFR(24)  x0 += ks2; x1 += ks0 + 2u;
    TFR(13) TFR(15) TFR(26) TFR(6)   x0 += ks0; x1 += ks1 + 3u;
    TFR(17) TFR(29) TFR(16) TFR(24)  x0 += ks1; x1 += ks2 + 4u;
    TFR(13) TFR(15) TFR(26) TFR(6)   x0 += ks2; x1 += ks0 + 5u;
#undef TFR
    o0 = x0; o1 = x1;
}

// partitionable random_bits: element e -> tf(key, 0, e), XOR halves
__device__ __forceinline__ uint32_t jax_bits32(uint32_t k0, uint32_t k1, uint32_t e) {
    uint32_t o0, o1;
    tf2x32(k0, k1, 0u, e, o0, o1);
    return o0 ^ o1;
}

// ---------------- XLA fast tanh — GPU variant (with_fma, clamp 7.99881) ----
__device__ __forceinline__ float xla_tanh(float x) {
    float ax = fabsf(x);
    float xc = fminf(fmaxf(x, -7.99881172180175781f), 7.99881172180175781f);
    float x2 = __fmul_rn(xc, xc);
    float num = -2.76076847742355e-16f;
    num = __fmaf_rn(x2, num, 2.00018790482477e-13f);
    num = __fmaf_rn(x2, num, -8.60467152213735e-11f);
    num = __fmaf_rn(x2, num, 5.12229709037114e-08f);
    num = __fmaf_rn(x2, num, 1.48572235717979e-05f);
    num = __fmaf_rn(x2, num, 6.37261928875436e-04f);
    num = __fmaf_rn(x2, num, 4.89352455891786e-03f);
    num = __fmul_rn(xc, num);
    float den = 1.19825839466702e-06f;
    den = __fmaf_rn(x2, den, 1.18534705686654e-04f);
    den = __fmaf_rn(x2, den, 2.26843463243900e-03f);
    den = __fmaf_rn(x2, den, 4.89352518554385e-03f);
    return (ax < 0.0004f) ? x : __fdiv_rn(num, den);
}

// LogisticExpander, GPU contraction: 0.5 + 0.5*t -> fma(0.5, t, 0.5)
__device__ __forceinline__ float xla_logistic(float x) {
    return __fmaf_rn(0.5f, xla_tanh(__fmul_rn(0.5f, x)), 0.5f);
}

// XLA f32 erf_inv polynomial — FMA Horner, log1p via libdevice
__device__ __forceinline__ float erfinv_xla(float x) {
    float x2 = __fmul_rn(x, x);
    float w = -log1pf(-x2);
    float p;
    if (w < 5.f) {
        w = __fsub_rn(w, 2.5f);
        p = 2.81022636e-08f;
        p = __fmaf_rn(p, w, 3.43273939e-07f);
        p = __fmaf_rn(p, w, -3.5233877e-06f);
        p = __fmaf_rn(p, w, -4.39150654e-06f);
        p = __fmaf_rn(p, w, 0.00021858087f);
        p = __fmaf_rn(p, w, -0.00125372503f);
        p = __fmaf_rn(p, w, -0.00417768164f);
        p = __fmaf_rn(p, w, 0.246640727f);
        p = __fmaf_rn(p, w, 1.50140941f);
    } else {
        w = __fsub_rn(sqrtf(w), 3.f);
        p = -0.000200214257f;
        p = __fmaf_rn(p, w, 0.000100950558f);
        p = __fmaf_rn(p, w, 0.00134934322f);
        p = __fmaf_rn(p, w, -0.00367342844f);
        p = __fmaf_rn(p, w, 0.00573950773f);
        p = __fmaf_rn(p, w, -0.0076224613f);
        p = __fmaf_rn(p, w, 0.00943887047f);
        p = __fmaf_rn(p, w, 1.00167406f);
        p = __fmaf_rn(p, w, 2.83297682f);
    }
    return __fmul_rn(p, x);
}

// jax.random.normal from raw bits: uniform(lo,1) then sqrt(2)*erfinv
__device__ __forceinline__ float jax_normal_bits(uint32_t bits) {
    float f = __fsub_rn(__uint_as_float((bits >> 9) | 0x3f800000u), 1.0f);
    const float lo = -0.99999994f;
    float v = __fmaf_rn(f, 2.0f, lo);
    v = fmaxf(lo, v);
    return __fmul_rn(1.41421356237309515f, erfinv_xla(v));
}

// ---------------- prep: transposes + variance terms ----------------
__global__ void prep_kernel(const float* __restrict__ g_whh,
                            const float* __restrict__ f_w1,
                            const float* __restrict__ f_w2,
                            const float* __restrict__ lvx,
                            const float* __restrict__ lvy,
                            const float* __restrict__ wih0,
                            const float* __restrict__ whh0,
                            const float* __restrict__ wih1,
                            const float* __restrict__ whh1,
                            const float* __restrict__ wih2,
                            const float* __restrict__ whh2,
                            const float* __restrict__ g_wih) {
    int idx = blockIdx.x * blockDim.x + threadIdx.x;
    int stride = gridDim.x * blockDim.x;
    for (int i = idx; i < 768 * LAT; i += stride) {
        int r = i / LAT, c = i % LAT;
        d_gwhhT[c * 768 + r] = g_whh[i];
    }
    for (int i = idx; i < LAT * LAT; i += stride) {
        int r = i / LAT, c = i % LAT;
        d_fw1T[c * LAT + r] = f_w1[i];
    }
    for (int i = idx; i < OUT_DIM * LAT; i += stride) {
        int r = i / LAT, c = i % LAT;
        d_fw2T[c * OUT_DIM + r] = f_w2[i];
    }
    // input-GRU weight transposes [192][64] -> [64][192]
    for (int i = idx; i < 192 * IN_DIM; i += stride) {
        int r = i / IN_DIM, c = i % IN_DIM;
        d_wihT[0][c * 192 + r] = wih0[i];  d_whhT[0][c * 192 + r] = whh0[i];
        d_wihT[1][c * 192 + r] = wih1[i];  d_whhT[1][c * 192 + r] = whh1[i];
        d_wihT[2][c * 192 + r] = wih2[i];  d_whhT[2][c * 192 + r] = whh2[i];
    }
    // g_wih [768][64] -> [64][768]
    for (int i = idx; i < 768 * IN_DIM; i += stride) {
        int r = i / IN_DIM, c = i % IN_DIM;
        d_gwihT[c * 768 + r] = g_wih[i];
    }
    for (int i = idx; i < OUT_DIM; i += stride) d_vary[i] = expf(lvy[i]);
    for (int i = idx; i < LAT; i += stride) d_stdx[i] = expf(__fmul_rn(0.5f, lvx[i]));
    if (idx == 0) {
        float s = 0.f;
        for (int o = 0; o < OUT_DIM; o++) s = __fadd_rn(s, lvy[o]);
        d_slv = s;
    }
}

// ---------------- input GRU: gi = X @ Wih^T (coalesced transposed W) -------
__global__ void gi_gemm_kernel(int layer,
                               const float* __restrict__ X,
                               const float* __restrict__ bias,
                               float* __restrict__ out) {
    __shared__ float xs[IN_DIM];
    int row = blockIdx.x, j = threadIdx.x;   // 192 threads
    if (j < IN_DIM) xs[j] = X[row * IN_DIM + j];
    __syncthreads();
    const float* WT = d_wihT[layer];
    float acc = 0.f;
#pragma unroll 8
    for (int k = 0; k < IN_DIM; k++) acc = __fmaf_rn(xs[k], WT[k * 192 + j], acc);
    out[(size_t)row * 192 + j] = __fadd_rn(acc, bias[j]);
}

// ---------------- input GRU recurrence (coalesced transposed Whh) ----------
__global__ void gru_rec_kernel(int layer,
                               const float* __restrict__ gi,
                               const float* __restrict__ bhh,
                               float* __restrict__ up) {
    __shared__ float h[IN_DIM];
    __shared__ float gh[192];
    int b = blockIdx.x, j = threadIdx.x;   // 192 threads
    if (j < IN_DIM) h[j] = 0.f;
    __syncthreads();
    const float* WT = d_whhT[layer];
    float bj = bhh[j];
    for (int t = 0; t < T_STEPS; t++) {
        float acc = 0.f;
#pragma unroll 8
        for (int k = 0; k < IN_DIM; k++) acc = __fmaf_rn(h[k], WT[k * 192 + j], acc);
        gh[j] = __fadd_rn(acc, bj);
        __syncthreads();
        if (j < IN_DIM) {
            const float* g = gi + (size_t)(t * BS + b) * 192;
            float r = xla_logistic(__fadd_rn(g[j], gh[j]));
            float z = xla_logistic(__fadd_rn(g[IN_DIM + j], gh[IN_DIM + j]));
            float nn = xla_tanh(__fmaf_rn(r, gh[2 * IN_DIM + j], g[2 * IN_DIM + j]));
            float zh = __fmul_rn(z, h[j]);
            float hv = __fmaf_rn(__fsub_rn(1.f, z), nn, zh);
            h[j] = hv;
            up[(size_t)(t * BS + b) * IN_DIM + j] = hv;
        }
        __syncthreads();
    }
}

// ---------------- particle-cell input gates (coalesced transposed g_wih) ---
__global__ void gip_gemm_kernel(const float* __restrict__ X,
                                const float* __restrict__ bias,
                                float* __restrict__ out) {
    __shared__ float xs[IN_DIM];
    int row = blockIdx.x, j = threadIdx.x;  // 768 threads
    if (j < IN_DIM) xs[j] = X[row * IN_DIM + j];
    __syncthreads();
    float acc = 0.f;
#pragma unroll 8
    for (int k = 0; k < IN_DIM; k++) acc = __fmaf_rn(xs[k], d_gwihT[k * 768 + j], acc);
    out[(size_t)row * 768 + j] = __fadd_rn(acc, bias[j]);
}

// ---------------- fused step: resample + gather + GRU cell + noise + FFN ---
// 512 threads: j = tid & 255 (latent), half = tid >> 8 owns particles
// [half*8, half*8+8). FFN2: one output element per thread.
__global__ void __launch_bounds__(512, 1)
step_kernel(int k, int first,
            const float* __restrict__ xprev, float* __restrict__ xnew,
            float* __restrict__ out, const float* __restrict__ y,
            uint32_t nk0, uint32_t nk1, uint32_t rk0, uint32_t rk1,
            const float* __restrict__ g_bhh,
            const float* __restrict__ f_b1,
            const float* __restrict__ f_b2) {
    __shared__ float R1[256 * 17];   // gathered H, later FFN1 hidden
    __shared__ float R2[256 * 17];   // x (post-noise)
    __shared__ float lp[NPART];
    __shared__ int   sidx[16];
    int tid = threadIdx.x;
    int j = tid & 255, half = tid >> 8;
    int wid = tid >> 5, lane = tid & 31;
    int b = blockIdx.y, p0 = blockIdx.x * 16;

    // ---- resample (k>0): logp for all 128 particles + argmax for our 16 ---
    if (!first) {
        const float* yp = y + (size_t)((k - 1) * BS + b) * OUT_DIM;
        float ypv = yp[lane];
        float vv = d_vary[lane];
        for (int p = wid; p < NPART; p += 16) {
            const float* yh = out + (size_t)(((k - 1) * BS + b) * NPART + p) * OUT_DIM;
            float d = __fsub_rn(yh[lane], ypv);
            float v = __fdiv_rn(__fmul_rn(d, d), vv);
#pragma unroll
            for (int off = 16; off; off >>= 1)
                v = __fadd_rn(v, __shfl_down_sync(0xffffffffu, v, off));
            if (lane == 0)
                lp[p] = __fmul_rn(-0.5f, __fadd_rn(__fadd_rn(v, d_slv), C32LOG2PI));
        }
        __syncthreads();

        // warp wid resamples particle slot p0 + wid (identical per-slot code)
        {
            int pp = p0 + wid;
            float best = -3.4e38f; int bi = 0;
#pragma unroll
            for (int q = 0; q < 4; q++) {
                int n = lane * 4 + q;
                uint32_t e = ((uint32_t)(b * NPART + pp) << 7) | (uint32_t)n;
                uint32_t bits = jax_bits32(rk0, rk1, e);
                float f = __fsub_rn(__uint_as_float((bits >> 9) | 0x3f800000u), 1.0f);
                float val = __fadd_rn(__fmul_rn(f, 1.0f), 1.17549435e-38f);
                val = fmaxf(1.17549435e-38f, val);
                float l1 = logf(val);
                float g = -logf(-l1);
                float tot = __fadd_rn(g, lp[n]);
                if (tot > best) { best = tot; bi = n; }
            }
            for (int off = 16; off; off >>= 1) {
                float ov = __shfl_down_sync(0xffffffffu, best, off);
                int   oi = __shfl_down_sync(0xffffffffu, bi, off);
                if (ov > best || (ov == best && oi < bi)) { best = ov; bi = oi; }
            }
            if (lane == 0) sidx[wid] = bi;
        }
        __syncthreads();
    }

    // ---- gather resampled particles (each half loads its 8) ----
    float hp_reg[8];
    if (first) {
#pragma unroll
        for (int q = 0; q < 8; q++) { hp_reg[q] = 0.f; R1[j * 17 + half * 8 + q] = 0.f; }
    } else {
#pragma unroll
        for (int q = 0; q < 8; q++) {
            int p = half * 8 + q;
            int ip = sidx[p];
            float hv = xprev[(size_t)(b * NPART + ip) * LAT + j];
            hp_reg[q] = hv;
            R1[j * 17 + p] = hv;
        }
    }
    __syncthreads();

    // ---- gh = h @ g_whh^T (ascending l, single accumulator, fma) ----
    float ar[8], az[8], an[8];
#pragma unroll
    for (int q = 0; q < 8; q++) { ar[q] = 0.f; az[q] = 0.f; an[q] = 0.f; }
    if (!first) {
#pragma unroll 4
        for (int l = 0; l < LAT; l++) {
            float wr = d_gwhhT[l * 768 + j];
            float wz = d_gwhhT[l * 768 + 256 + j];
            float wn = d_gwhhT[l * 768 + 512 + j];
#pragma unroll
            for (int q = 0; q < 8; q++) {
                float hv = R1[l * 17 + half * 8 + q];
                ar[q] = __fmaf_rn(wr, hv, ar[q]);
                az[q] = __fmaf_rn(wz, hv, az[q]);
                an[q] = __fmaf_rn(wn, hv, an[q]);
            }
        }
    }

    // ---- gates + noise (GPU-contracted forms) ----
    const float* gib = d_giP + (size_t)(k * BS + b) * 768;
    float ir = gib[j], iz = gib[256 + j], inn = gib[512 + j];
    float br = g_bhh[j], bz = g_bhh[256 + j], bn = g_bhh[512 + j];
    float sx = d_stdx[j];
#pragma unroll
    for (int q = 0; q < 8; q++) {
        int p = half * 8 + q;
        float ghr = __fadd_rn(ar[q], br);
        float ghz = __fadd_rn(az[q], bz);
        float ghn = __fadd_rn(an[q], bn);
        float r = xla_logistic(__fadd_rn(ir, ghr));
        float z = xla_logistic(__fadd_rn(iz, ghz));
        float nn = xla_tanh(__fmaf_rn(r, ghn, inn));
        float zh = __fmul_rn(z, hp_reg[q]);
        float xv = __fmaf_rn(__fsub_rn(1.f, z), nn, zh);
        uint32_t e = ((uint32_t)(b * NPART + p0 + p) << 8) | (uint32_t)j;
        uint32_t bits = jax_bits32(nk0, nk1, e);
        xv = __fmaf_rn(jax_normal_bits(bits), sx, xv);
        xnew[(size_t)(b * NPART + p0 + p) * LAT + j] = xv;
        R2[j * 17 + p] = xv;
    }
    __syncthreads();

    // ---- FFN1: hidden = relu(x @ f_w1^T + b1) ----
    float a2[8];
#pragma unroll
    for (int q = 0; q < 8; q++) a2[q] = 0.f;
#pragma unroll 4
    for (int l = 0; l < LAT; l++) {
        float w = d_fw1T[l * LAT + j];
#pragma unroll
        for (int q = 0; q < 8; q++) a2[q] = __fmaf_rn(w, R2[l * 17 + half * 8 + q], a2[q]);
    }
    float bb1 = f_b1[j];
#pragma unroll
    for (int q = 0; q < 8; q++)
        R1[j * 17 + half * 8 + q] = fmaxf(__fadd_rn(a2[q], bb1), 0.f);
    __syncthreads();

    // ---- FFN2: one output element per thread (ascending l, fma) ----
    {
        int o = tid & 31, pf = tid >> 5;   // 16 particles x 32 outs = 512
        float acc = 0.f;
#pragma unroll 8
        for (int l = 0; l < LAT; l++)
            acc = __fmaf_rn(d_fw2T[l * OUT_DIM + o], R1[l * 17 + pf], acc);
        out[(size_t)((k * BS + b) * NPART + p0 + pf) * OUT_DIM + o] =
            __fadd_rn(acc, f_b2[o]);
    }
}

// ---------------- host ----------------
extern "C" void kernel_launch(void* const* d_in, const int* in_sizes, int n_in,
                              void* d_out, int out_size) {
    const float *u = 0, *y = 0, *g_wih = 0, *g_whh = 0, *g_bih = 0, *g_bhh = 0;
    const float *f_w1 = 0, *f_b1 = 0, *f_w2 = 0, *f_b2 = 0, *lvx = 0, *lvy = 0;
    const float *wih[3] = {0, 0, 0}, *whh[3] = {0, 0, 0}, *bih[3] = {0, 0, 0}, *bhh[3] = {0, 0, 0};
    int c12288 = 0, c192 = 0, c768 = 0, c256 = 0, c32 = 0;
    for (int i = 0; i < n_in; i++) {
        int s = in_sizes[i];
        const float* p = (const float*)d_in[i];
        if (s == 262144) u = p;
        else if (s == 131072) y = p;
        else if (s == 49152) g_wih = p;
        else if (s == 196608) g_whh = p;
        else if (s == 768) { if (c768++ == 0) g_bih = p; else g_bhh = p; }
        else if (s == 65536) f_w1 = p;
        else if (s == 8192) f_w2 = p;
        else if (s == 256) { if (c256++ == 0) f_b1 = p; else lvx = p; }
        else if (s == 32) { if (c32++ == 0) f_b2 = p; else lvy = p; }
        else if (s == 12288) { int t = c12288++; if ((t & 1) == 0) wih[t / 2] = p; else whh[t / 2] = p; }
        else if (s == 192) { int t = c192++; if ((t & 1) == 0) bih[t / 2] = p; else bhh[t / 2] = p; }
    }

    // JAX key derivation (threefry_partitionable):
    //   base = key(42); fold_in(base,m) = tf(base,0,m); split(key,T)[t] = tf(key,0,t)
    uint32_t kr0, kr1, kn0, kn1;
    tf2x32(0u, 42u, 0u, 1u, kr0, kr1);
    tf2x32(0u, 42u, 0u, 2u, kn0, kn1);
    static uint32_t rk[T_STEPS][2], nk[T_STEPS][2];
    for (int t = 0; t < T_STEPS; t++) {
        tf2x32(kr0, kr1, 0u, (uint32_t)t, rk[t][0], rk[t][1]);
        tf2x32(kn0, kn1, 0u, (uint32_t)t, nk[t][0], nk[t][1]);
    }

    void *pgi, *pupA, *pupB, *pgiP, *px;
    cudaGetSymbolAddress(&pgi, d_gi);
    cudaGetSymbolAddress(&pupA, d_upA);
    cudaGetSymbolAddress(&pupB, d_upB);
    cudaGetSymbolAddress(&pgiP, d_giP);
    cudaGetSymbolAddress(&px, d_x);
    float* gi = (float*)pgi;
    float* upA = (float*)pupA;
    float* upB = (float*)pupB;
    float* giP = (float*)pgiP;
    float* xb = (float*)px;
    float* xbuf[2] = {xb, xb + BS * NPART * LAT};
    float* fout = (float*)d_out;

    prep_kernel<<<128, 256>>>(g_whh, f_w1, f_w2, lvx, lvy,
                              wih[0], whh[0], wih[1], whh[1], wih[2], whh[2],
                              g_wih);

    // 3-layer input GRU (coalesced transposed weights)
    gi_gemm_kernel<<<T_STEPS * BS, 192>>>(0, u, bih[0], gi);
    gru_rec_kernel<<<BS, 192>>>(0, gi, bhh[0], upA);
    gi_gemm_kernel<<<T_STEPS * BS, 192>>>(1, upA, bih[1], gi);
    gru_rec_kernel<<<BS, 192>>>(1, gi, bhh[1], upB);
    gi_gemm_kernel<<<T_STEPS * BS, 192>>>(2, upB, bih[2], gi);
    gru_rec_kernel<<<BS, 192>>>(2, gi, bhh[2], upA);

    // particle-cell input gates for all steps
    gip_gemm_kernel<<<T_STEPS * BS, 768>>>(upA, g_bih, giP);

    // sequential particle filter — fused resample+update, one launch per step
    for (int k = 0; k < T_STEPS; k++) {
        int cur = k & 1, prev = cur ^ 1;
        step_kernel<<<dim3(8, BS), 512>>>(k, (k == 0) ? 1 : 0,
                                          xbuf[prev], xbuf[cur], fout, y,
                                          nk[k][0], nk[k][1],
                                          rk[k][0], rk[k][1],
                                          g_bhh, f_b1, f_b2);
    }
}

// round 16
// speedup vs baseline: 1.8390x; 1.0873x over previous
#include <cuda_runtime.h>
#include <cstdint>
#include <math.h>

// ---------------- constants ----------------
#define T_STEPS 256
#define BS      16
#define IN_DIM  64
#define LAT     256
#define OUT_DIM 32
#define NPART   128
#define C32LOG2PI 58.81206612509905f

// ---------------- device scratch (no cudaMalloc allowed) ----------------
__device__ float d_gi  [T_STEPS*BS*192];       // 3*IN gates for input GRU
__device__ float d_upA [T_STEPS*BS*IN_DIM];
__device__ float d_upB [T_STEPS*BS*IN_DIM];
__device__ float d_giP [T_STEPS*BS*768];       // 3*LAT input gates for particle cell
__device__ float4 d_gwhh4[LAT*LAT];            // packed (wr,wz,wn,0) [l*256+j]
__device__ float d_fw1T [LAT*LAT];             // f_w1 transposed  [256][256]
__device__ float d_fw2T [LAT*OUT_DIM];         // f_w2 transposed  [256][32]
__device__ float d_wihT [3][IN_DIM*192];       // w_ih_l transposed [64][192]
__device__ float d_whhT [3][IN_DIM*192];       // w_hh_l transposed [64][192]
__device__ float d_gwihT[IN_DIM*768];          // g_wih transposed  [64][768]
__device__ float d_x   [2][BS*NPART*LAT];      // particle ping-pong
__device__ float d_vary[OUT_DIM];
__device__ float d_stdx[LAT];
__device__ float d_slv;

// ---------------- threefry2x32 (JAX-exact) ---------------------------------
__host__ __device__ __forceinline__ void tf2x32(uint32_t k0, uint32_t k1,
                                                uint32_t x0, uint32_t x1,
                                                uint32_t& o0, uint32_t& o1) {
    uint32_t ks0 = k0, ks1 = k1, ks2 = 0x1BD11BDAu ^ k0 ^ k1;
    x0 += ks0; x1 += ks1;
#define TFR(r) { x0 += x1; x1 = (x1 << (r)) | (x1 >> (32 - (r))); x1 ^= x0; }
    TFR(13) TFR(15) TFR(26) TFR(6)   x0 += ks1; x1 += ks2 + 1u;
    TFR(17) TFR(29) TFR(16) TFR(24)  x0 += ks2; x1 += ks0 + 2u;
    TFR(13) TFR(15) TFR(26) TFR(6)   x0 += ks0; x1 += ks1 + 3u;
    TFR(17) TFR(29) TFR(16) TFR(24)  x0 += ks1; x1 += ks2 + 4u;
    TFR(13) TFR(15) TFR(26) TFR(6)   x0 += ks2; x1 += ks0 + 5u;
#undef TFR
    o0 = x0; o1 = x1;
}

// partitionable random_bits: element e -> tf(key, 0, e), XOR halves
__device__ __forceinline__ uint32_t jax_bits32(uint32_t k0, uint32_t k1, uint32_t e) {
    uint32_t o0, o1;
    tf2x32(k0, k1, 0u, e, o0, o1);
    return o0 ^ o1;
}

// ---------------- XLA fast tanh — GPU variant (with_fma, clamp 7.99881) ----
__device__ __forceinline__ float xla_tanh(float x) {
    float ax = fabsf(x);
    float xc = fminf(fmaxf(x, -7.99881172180175781f), 7.99881172180175781f);
    float x2 = __fmul_rn(xc, xc);
    float num = -2.76076847742355e-16f;
    num = __fmaf_rn(x2, num, 2.00018790482477e-13f);
    num = __fmaf_rn(x2, num, -8.60467152213735e-11f);
    num = __fmaf_rn(x2, num, 5.12229709037114e-08f);
    num = __fmaf_rn(x2, num, 1.48572235717979e-05f);
    num = __fmaf_rn(x2, num, 6.37261928875436e-04f);
    num = __fmaf_rn(x2, num, 4.89352455891786e-03f);
    num = __fmul_rn(xc, num);
    float den = 1.19825839466702e-06f;
    den = __fmaf_rn(x2, den, 1.18534705686654e-04f);
    den = __fmaf_rn(x2, den, 2.26843463243900e-03f);
    den = __fmaf_rn(x2, den, 4.89352518554385e-03f);
    return (ax < 0.0004f) ? x : __fdiv_rn(num, den);
}

// LogisticExpander, GPU contraction: 0.5 + 0.5*t -> fma(0.5, t, 0.5)
__device__ __forceinline__ float xla_logistic(float x) {
    return __fmaf_rn(0.5f, xla_tanh(__fmul_rn(0.5f, x)), 0.5f);
}

// XLA f32 erf_inv polynomial — FMA Horner, log1p via libdevice
__device__ __forceinline__ float erfinv_xla(float x) {
    float x2 = __fmul_rn(x, x);
    float w = -log1pf(-x2);
    float p;
    if (w < 5.f) {
        w = __fsub_rn(w, 2.5f);
        p = 2.81022636e-08f;
        p = __fmaf_rn(p, w, 3.43273939e-07f);
        p = __fmaf_rn(p, w, -3.5233877e-06f);
        p = __fmaf_rn(p, w, -4.39150654e-06f);
        p = __fmaf_rn(p, w, 0.00021858087f);
        p = __fmaf_rn(p, w, -0.00125372503f);
        p = __fmaf_rn(p, w, -0.00417768164f);
        p = __fmaf_rn(p, w, 0.246640727f);
        p = __fmaf_rn(p, w, 1.50140941f);
    } else {
        w = __fsub_rn(sqrtf(w), 3.f);
        p = -0.000200214257f;
        p = __fmaf_rn(p, w, 0.000100950558f);
        p = __fmaf_rn(p, w, 0.00134934322f);
        p = __fmaf_rn(p, w, -0.00367342844f);
        p = __fmaf_rn(p, w, 0.00573950773f);
        p = __fmaf_rn(p, w, -0.0076224613f);
        p = __fmaf_rn(p, w, 0.00943887047f);
        p = __fmaf_rn(p, w, 1.00167406f);
        p = __fmaf_rn(p, w, 2.83297682f);
    }
    return __fmul_rn(p, x);
}

// jax.random.normal from raw bits: uniform(lo,1) then sqrt(2)*erfinv
__device__ __forceinline__ float jax_normal_bits(uint32_t bits) {
    float f = __fsub_rn(__uint_as_float((bits >> 9) | 0x3f800000u), 1.0f);
    const float lo = -0.99999994f;
    float v = __fmaf_rn(f, 2.0f, lo);
    v = fmaxf(lo, v);
    return __fmul_rn(1.41421356237309515f, erfinv_xla(v));
}

// ---------------- prep: transposes + packing + variance terms --------------
__global__ void prep_kernel(const float* __restrict__ g_whh,
                            const float* __restrict__ f_w1,
                            const float* __restrict__ f_w2,
                            const float* __restrict__ lvx,
                            const float* __restrict__ lvy,
                            const float* __restrict__ wih0,
                            const float* __restrict__ whh0,
                            const float* __restrict__ wih1,
                            const float* __restrict__ whh1,
                            const float* __restrict__ wih2,
                            const float* __restrict__ whh2,
                            const float* __restrict__ g_wih) {
    int idx = blockIdx.x * blockDim.x + threadIdx.x;
    int stride = gridDim.x * blockDim.x;
    // packed g_whh: row j of g_whh is [768] = (r[256], z[256], n[256]) per
    // PyTorch gate order over output dim; we need, for (l, j):
    // wr = g_whh[j*256? no: g_whh is [768][256]; element (row=gate*256+j, col=l)
    for (int i = idx; i < LAT * LAT; i += stride) {
        int l = i / LAT, j = i % LAT;
        float4 v;
        v.x = g_whh[(0 * LAT + j) * LAT + l];
        v.y = g_whh[(1 * LAT + j) * LAT + l];
        v.z = g_whh[(2 * LAT + j) * LAT + l];
        v.w = 0.f;
        d_gwhh4[l * LAT + j] = v;
    }
    for (int i = idx; i < LAT * LAT; i += stride) {
        int r = i / LAT, c = i % LAT;
        d_fw1T[c * LAT + r] = f_w1[i];
    }
    for (int i = idx; i < OUT_DIM * LAT; i += stride) {
        int r = i / LAT, c = i % LAT;
        d_fw2T[c * OUT_DIM + r] = f_w2[i];
    }
    // input-GRU weight transposes [192][64] -> [64][192]
    for (int i = idx; i < 192 * IN_DIM; i += stride) {
        int r = i / IN_DIM, c = i % IN_DIM;
        d_wihT[0][c * 192 + r] = wih0[i];  d_whhT[0][c * 192 + r] = whh0[i];
        d_wihT[1][c * 192 + r] = wih1[i];  d_whhT[1][c * 192 + r] = whh1[i];
        d_wihT[2][c * 192 + r] = wih2[i];  d_whhT[2][c * 192 + r] = whh2[i];
    }
    // g_wih [768][64] -> [64][768]
    for (int i = idx; i < 768 * IN_DIM; i += stride) {
        int r = i / IN_DIM, c = i % IN_DIM;
        d_gwihT[c * 768 + r] = g_wih[i];
    }
    for (int i = idx; i < OUT_DIM; i += stride) d_vary[i] = expf(lvy[i]);
    for (int i = idx; i < LAT; i += stride) d_stdx[i] = expf(__fmul_rn(0.5f, lvx[i]));
    if (idx == 0) {
        float s = 0.f;
        for (int o = 0; o < OUT_DIM; o++) s = __fadd_rn(s, lvy[o]);
        d_slv = s;
    }
}

// ---------------- input GRU: gi = X @ Wih^T (coalesced transposed W) -------
__global__ void gi_gemm_kernel(int layer,
                               const float* __restrict__ X,
                               const float* __restrict__ bias,
                               float* __restrict__ out) {
    __shared__ float xs[IN_DIM];
    int row = blockIdx.x, j = threadIdx.x;   // 192 threads
    if (j < IN_DIM) xs[j] = X[row * IN_DIM + j];
    __syncthreads();
    const float* WT = d_wihT[layer];
    float acc = 0.f;
#pragma unroll 8
    for (int k = 0; k < IN_DIM; k++) acc = __fmaf_rn(xs[k], WT[k * 192 + j], acc);
    out[(size_t)row * 192 + j] = __fadd_rn(acc, bias[j]);
}

// ---------------- input GRU recurrence (coalesced transposed Whh) ----------
__global__ void gru_rec_kernel(int layer,
                               const float* __restrict__ gi,
                               const float* __restrict__ bhh,
                               float* __restrict__ up) {
    __shared__ float h[IN_DIM];
    __shared__ float gh[192];
    int b = blockIdx.x, j = threadIdx.x;   // 192 threads
    if (j < IN_DIM) h[j] = 0.f;
    __syncthreads();
    const float* WT = d_whhT[layer];
    float bj = bhh[j];
    for (int t = 0; t < T_STEPS; t++) {
        float acc = 0.f;
#pragma unroll 8
        for (int k = 0; k < IN_DIM; k++) acc = __fmaf_rn(h[k], WT[k * 192 + j], acc);
        gh[j] = __fadd_rn(acc, bj);
        __syncthreads();
        if (j < IN_DIM) {
            const float* g = gi + (size_t)(t * BS + b) * 192;
            float r = xla_logistic(__fadd_rn(g[j], gh[j]));
            float z = xla_logistic(__fadd_rn(g[IN_DIM + j], gh[IN_DIM + j]));
            float nn = xla_tanh(__fmaf_rn(r, gh[2 * IN_DIM + j], g[2 * IN_DIM + j]));
            float zh = __fmul_rn(z, h[j]);
            float hv = __fmaf_rn(__fsub_rn(1.f, z), nn, zh);
            h[j] = hv;
            up[(size_t)(t * BS + b) * IN_DIM + j] = hv;
        }
        __syncthreads();
    }
}

// ---------------- particle-cell input gates (coalesced transposed g_wih) ---
__global__ void gip_gemm_kernel(const float* __restrict__ X,
                                const float* __restrict__ bias,
                                float* __restrict__ out) {
    __shared__ float xs[IN_DIM];
    int row = blockIdx.x, j = threadIdx.x;  // 768 threads
    if (j < IN_DIM) xs[j] = X[row * IN_DIM + j];
    __syncthreads();
    float acc = 0.f;
#pragma unroll 8
    for (int k = 0; k < IN_DIM; k++) acc = __fmaf_rn(xs[k], d_gwihT[k * 768 + j], acc);
    out[(size_t)row * 768 + j] = __fadd_rn(acc, bias[j]);
}

// ---------------- fused step: resample + gather + GRU cell + noise + FFN ---
// 512 threads: j = tid & 255 (latent), half = tid >> 8 owns 8 particles.
// Smem tiles stride 16 -> vectorized LDS.128 broadcast reads.
__global__ void __launch_bounds__(512, 1)
step_kernel(int k, int first,
            const float* __restrict__ xprev, float* __restrict__ xnew,
            float* __restrict__ out, const float* __restrict__ y,
            uint32_t nk0, uint32_t nk1, uint32_t rk0, uint32_t rk1,
            const float* __restrict__ g_bhh,
            const float* __restrict__ f_b1,
            const float* __restrict__ f_b2) {
    __shared__ float R1[256 * 16];   // gathered H, later FFN1 hidden
    __shared__ float R2[256 * 16];   // x (post-noise)
    __shared__ float lp[NPART];
    __shared__ int   sidx[16];
    int tid = threadIdx.x;
    int j = tid & 255, half = tid >> 8;
    int wid = tid >> 5, lane = tid & 31;
    int b = blockIdx.y, p0 = blockIdx.x * 16;
    int pbase = half * 8;

    // ---- resample (k>0): logp for all 128 particles + argmax for our 16 ---
    if (!first) {
        const float* yp = y + (size_t)((k - 1) * BS + b) * OUT_DIM;
        float ypv = yp[lane];
        float vv = d_vary[lane];
        for (int p = wid; p < NPART; p += 16) {
            const float* yh = out + (size_t)(((k - 1) * BS + b) * NPART + p) * OUT_DIM;
            float d = __fsub_rn(yh[lane], ypv);
            float v = __fdiv_rn(__fmul_rn(d, d), vv);
#pragma unroll
            for (int off = 16; off; off >>= 1)
                v = __fadd_rn(v, __shfl_down_sync(0xffffffffu, v, off));
            if (lane == 0)
                lp[p] = __fmul_rn(-0.5f, __fadd_rn(__fadd_rn(v, d_slv), C32LOG2PI));
        }
        __syncthreads();

        {
            int pp = p0 + wid;
            float best = -3.4e38f; int bi = 0;
#pragma unroll
            for (int q = 0; q < 4; q++) {
                int n = lane * 4 + q;
                uint32_t e = ((uint32_t)(b * NPART + pp) << 7) | (uint32_t)n;
                uint32_t bits = jax_bits32(rk0, rk1, e);
                float f = __fsub_rn(__uint_as_float((bits >> 9) | 0x3f800000u), 1.0f);
                float val = __fadd_rn(__fmul_rn(f, 1.0f), 1.17549435e-38f);
                val = fmaxf(1.17549435e-38f, val);
                float l1 = logf(val);
                float g = -logf(-l1);
                float tot = __fadd_rn(g, lp[n]);
                if (tot > best) { best = tot; bi = n; }
            }
            for (int off = 16; off; off >>= 1) {
                float ov = __shfl_down_sync(0xffffffffu, best, off);
                int   oi = __shfl_down_sync(0xffffffffu, bi, off);
                if (ov > best || (ov == best && oi < bi)) { best = ov; bi = oi; }
            }
            if (lane == 0) sidx[wid] = bi;
        }
        __syncthreads();
    }

    // ---- gather resampled particles (each half loads its 8) ----
    float hp_reg[8];
    if (first) {
#pragma unroll
        for (int q = 0; q < 8; q++) hp_reg[q] = 0.f;
        float4 z4 = make_float4(0.f, 0.f, 0.f, 0.f);
        *reinterpret_cast<float4*>(&R1[j * 16 + pbase])     = z4;
        *reinterpret_cast<float4*>(&R1[j * 16 + pbase + 4]) = z4;
    } else {
#pragma unroll
        for (int q = 0; q < 8; q++) {
            int ip = sidx[pbase + q];
            hp_reg[q] = xprev[(size_t)(b * NPART + ip) * LAT + j];
        }
        *reinterpret_cast<float4*>(&R1[j * 16 + pbase]) =
            make_float4(hp_reg[0], hp_reg[1], hp_reg[2], hp_reg[3]);
        *reinterpret_cast<float4*>(&R1[j * 16 + pbase + 4]) =
            make_float4(hp_reg[4], hp_reg[5], hp_reg[6], hp_reg[7]);
    }
    __syncthreads();

    // ---- gh = h @ g_whh^T (ascending l, single accumulator per output) ----
    float ar[8], az[8], an[8];
#pragma unroll
    for (int q = 0; q < 8; q++) { ar[q] = 0.f; az[q] = 0.f; an[q] = 0.f; }
    if (!first) {
        const float4* W4 = d_gwhh4;
#pragma unroll 4
        for (int l = 0; l < LAT; l++) {
            float4 w = __ldg(&W4[l * LAT + j]);
            float4 ha = *reinterpret_cast<const float4*>(&R1[l * 16 + pbase]);
            float4 hb = *reinterpret_cast<const float4*>(&R1[l * 16 + pbase + 4]);
            ar[0] = __fmaf_rn(w.x, ha.x, ar[0]); az[0] = __fmaf_rn(w.y, ha.x, az[0]); an[0] = __fmaf_rn(w.z, ha.x, an[0]);
            ar[1] = __fmaf_rn(w.x, ha.y, ar[1]); az[1] = __fmaf_rn(w.y, ha.y, az[1]); an[1] = __fmaf_rn(w.z, ha.y, an[1]);
            ar[2] = __fmaf_rn(w.x, ha.z, ar[2]); az[2] = __fmaf_rn(w.y, ha.z, az[2]); an[2] = __fmaf_rn(w.z, ha.z, an[2]);
            ar[3] = __fmaf_rn(w.x, ha.w, ar[3]); az[3] = __fmaf_rn(w.y, ha.w, az[3]); an[3] = __fmaf_rn(w.z, ha.w, an[3]);
            ar[4] = __fmaf_rn(w.x, hb.x, ar[4]); az[4] = __fmaf_rn(w.y, hb.x, az[4]); an[4] = __fmaf_rn(w.z, hb.x, an[4]);
            ar[5] = __fmaf_rn(w.x, hb.y, ar[5]); az[5] = __fmaf_rn(w.y, hb.y, az[5]); an[5] = __fmaf_rn(w.z, hb.y, an[5]);
            ar[6] = __fmaf_rn(w.x, hb.z, ar[6]); az[6] = __fmaf_rn(w.y, hb.z, az[6]); an[6] = __fmaf_rn(w.z, hb.z, an[6]);
            ar[7] = __fmaf_rn(w.x, hb.w, ar[7]); az[7] = __fmaf_rn(w.y, hb.w, az[7]); an[7] = __fmaf_rn(w.z, hb.w, an[7]);
        }
    }

    // ---- gates + noise (GPU-contracted forms) ----
    const float* gib = d_giP + (size_t)(k * BS + b) * 768;
    float ir = gib[j], iz = gib[256 + j], inn = gib[512 + j];
    float br = g_bhh[j], bz = g_bhh[256 + j], bn = g_bhh[512 + j];
    float sx = d_stdx[j];
    float xv_reg[8];
#pragma unroll
    for (int q = 0; q < 8; q++) {
        int p = pbase + q;
        float ghr = __fadd_rn(ar[q], br);
        float ghz = __fadd_rn(az[q], bz);
        float ghn = __fadd_rn(an[q], bn);
        float r = xla_logistic(__fadd_rn(ir, ghr));
        float z = xla_logistic(__fadd_rn(iz, ghz));
        float nn = xla_tanh(__fmaf_rn(r, ghn, inn));
        float zh = __fmul_rn(z, hp_reg[q]);
        float xv = __fmaf_rn(__fsub_rn(1.f, z), nn, zh);
        uint32_t e = ((uint32_t)(b * NPART + p0 + p) << 8) | (uint32_t)j;
        uint32_t bits = jax_bits32(nk0, nk1, e);
        xv = __fmaf_rn(jax_normal_bits(bits), sx, xv);
        xnew[(size_t)(b * NPART + p0 + p) * LAT + j] = xv;
        xv_reg[q] = xv;
    }
    *reinterpret_cast<float4*>(&R2[j * 16 + pbase]) =
        make_float4(xv_reg[0], xv_reg[1], xv_reg[2], xv_reg[3]);
    *reinterpret_cast<float4*>(&R2[j * 16 + pbase + 4]) =
        make_float4(xv_reg[4], xv_reg[5], xv_reg[6], xv_reg[7]);
    __syncthreads();

    // ---- FFN1: hidden = relu(x @ f_w1^T + b1) ----
    float a2[8];
#pragma unroll
    for (int q = 0; q < 8; q++) a2[q] = 0.f;
#pragma unroll 4
    for (int l = 0; l < LAT; l++) {
        float w = __ldg(&d_fw1T[l * LAT + j]);
        float4 xa = *reinterpret_cast<const float4*>(&R2[l * 16 + pbase]);
        float4 xb = *reinterpret_cast<const float4*>(&R2[l * 16 + pbase + 4]);
        a2[0] = __fmaf_rn(w, xa.x, a2[0]);
        a2[1] = __fmaf_rn(w, xa.y, a2[1]);
        a2[2] = __fmaf_rn(w, xa.z, a2[2]);
        a2[3] = __fmaf_rn(w, xa.w, a2[3]);
        a2[4] = __fmaf_rn(w, xb.x, a2[4]);
        a2[5] = __fmaf_rn(w, xb.y, a2[5]);
        a2[6] = __fmaf_rn(w, xb.z, a2[6]);
        a2[7] = __fmaf_rn(w, xb.w, a2[7]);
    }
    float bb1 = f_b1[j];
    float h1[8];
#pragma unroll
    for (int q = 0; q < 8; q++) h1[q] = fmaxf(__fadd_rn(a2[q], bb1), 0.f);
    __syncthreads();   // R1 reuse: ensure gh phase fully done (it is) & prior reads done
    *reinterpret_cast<float4*>(&R1[j * 16 + pbase]) =
        make_float4(h1[0], h1[1], h1[2], h1[3]);
    *reinterpret_cast<float4*>(&R1[j * 16 + pbase + 4]) =
        make_float4(h1[4], h1[5], h1[6], h1[7]);
    __syncthreads();

    // ---- FFN2: one output element per thread (ascending l, fma) ----
    {
        int o = tid & 31, pf = tid >> 5;   // 16 particles x 32 outs = 512
        float acc = 0.f;
#pragma unroll 8
        for (int l = 0; l < LAT; l++)
            acc = __fmaf_rn(__ldg(&d_fw2T[l * OUT_DIM + o]), R1[l * 16 + pf], acc);
        out[(size_t)((k * BS + b) * NPART + p0 + pf) * OUT_DIM + o] =
            __fadd_rn(acc, f_b2[o]);
    }
}

// ---------------- host ----------------
extern "C" void kernel_launch(void* const* d_in, const int* in_sizes, int n_in,
                              void* d_out, int out_size) {
    const float *u = 0, *y = 0, *g_wih = 0, *g_whh = 0, *g_bih = 0, *g_bhh = 0;
    const float *f_w1 = 0, *f_b1 = 0, *f_w2 = 0, *f_b2 = 0, *lvx = 0, *lvy = 0;
    const float *wih[3] = {0, 0, 0}, *whh[3] = {0, 0, 0}, *bih[3] = {0, 0, 0}, *bhh[3] = {0, 0, 0};
    int c12288 = 0, c192 = 0, c768 = 0, c256 = 0, c32 = 0;
    for (int i = 0; i < n_in; i++) {
        int s = in_sizes[i];
        const float* p = (const float*)d_in[i];
        if (s == 262144) u = p;
        else if (s == 131072) y = p;
        else if (s == 49152) g_wih = p;
        else if (s == 196608) g_whh = p;
        else if (s == 768) { if (c768++ == 0) g_bih = p; else g_bhh = p; }
        else if (s == 65536) f_w1 = p;
        else if (s == 8192) f_w2 = p;
        else if (s == 256) { if (c256++ == 0) f_b1 = p; else lvx = p; }
        else if (s == 32) { if (c32++ == 0) f_b2 = p; else lvy = p; }
        else if (s == 12288) { int t = c12288++; if ((t & 1) == 0) wih[t / 2] = p; else whh[t / 2] = p; }
        else if (s == 192) { int t = c192++; if ((t & 1) == 0) bih[t / 2] = p; else bhh[t / 2] = p; }
    }

    // JAX key derivation (threefry_partitionable):
    //   base = key(42); fold_in(base,m) = tf(base,0,m); split(key,T)[t] = tf(key,0,t)
    uint32_t kr0, kr1, kn0, kn1;
    tf2x32(0u, 42u, 0u, 1u, kr0, kr1);
    tf2x32(0u, 42u, 0u, 2u, kn0, kn1);
    static uint32_t rk[T_STEPS][2], nk[T_STEPS][2];
    for (int t = 0; t < T_STEPS; t++) {
        tf2x32(kr0, kr1, 0u, (uint32_t)t, rk[t][0], rk[t][1]);
        tf2x32(kn0, kn1, 0u, (uint32_t)t, nk[t][0], nk[t][1]);
    }

    void *pgi, *pupA, *pupB, *pgiP, *px;
    cudaGetSymbolAddress(&pgi, d_gi);
    cudaGetSymbolAddress(&pupA, d_upA);
    cudaGetSymbolAddress(&pupB, d_upB);
    cudaGetSymbolAddress(&pgiP, d_giP);
    cudaGetSymbolAddress(&px, d_x);
    float* gi = (float*)pgi;
    float* upA = (float*)pupA;
    float* upB = (float*)pupB;
    float* giP = (float*)pgiP;
    float* xb = (float*)px;
    float* xbuf[2] = {xb, xb + BS * NPART * LAT};
    float* fout = (float*)d_out;

    prep_kernel<<<128, 256>>>(g_whh, f_w1, f_w2, lvx, lvy,
                              wih[0], whh[0], wih[1], whh[1], wih[2], whh[2],
                              g_wih);

    // 3-layer input GRU (coalesced transposed weights)
    gi_gemm_kernel<<<T_STEPS * BS, 192>>>(0, u, bih[0], gi);
    gru_rec_kernel<<<BS, 192>>>(0, gi, bhh[0], upA);
    gi_gemm_kernel<<<T_STEPS * BS, 192>>>(1, upA, bih[1], gi);
    gru_rec_kernel<<<BS, 192>>>(1, gi, bhh[1], upB);
    gi_gemm_kernel<<<T_STEPS * BS, 192>>>(2, upB, bih[2], gi);
    gru_rec_kernel<<<BS, 192>>>(2, gi, bhh[2], upA);

    // particle-cell input gates for all steps
    gip_gemm_kernel<<<T_STEPS * BS, 768>>>(upA, g_bih, giP);

    // sequential particle filter — fused resample+update, one launch per step
    for (int k = 0; k < T_STEPS; k++) {
        int cur = k & 1, prev = cur ^ 1;
        step_kernel<<<dim3(8, BS), 512>>>(k, (k == 0) ? 1 : 0,
                                          xbuf[prev], xbuf[cur], fout, y,
                                          nk[k][0], nk[k][1],
                                          rk[k][0], rk[k][1],
                                          g_bhh, f_b1, f_b2);
    }
}